// round 11
// baseline (speedup 1.0000x reference)
#include <cuda_runtime.h>
#include <cuda_fp16.h>
#include <cstdint>

#define B_DIM 16
#define N_DIM 2048
#define DIN   128
#define DQv   64

// Qp/Kp: fp16 pair-interleaved words, 32 words per row.
__device__ uint32_t g_QpU[B_DIM * N_DIM * 32];
__device__ uint32_t g_KpU[B_DIM * N_DIM * 32];
// x prepacked: [b][mt(32)][kk(4)][d(128)][q(8)] fp16x2 words (pairs across rows).
__device__ uint32_t g_Xh[B_DIM * 32 * 4096];

#define SCALE_LOG2E 0.180336879f
#define MASK_NEG    -30000.0f

__device__ __forceinline__ uint32_t packh2(float lo, float hi) {
    __half2 h = __floats2half2_rn(lo, hi);
    return *reinterpret_cast<uint32_t*>(&h);
}
__device__ __forceinline__ uint32_t prmt(uint32_t a, uint32_t b, uint32_t sel) {
    uint32_t d;
    asm("prmt.b32 %0, %1, %2, %3;" : "=r"(d) : "r"(a), "r"(b), "r"(sel));
    return d;
}
__device__ __forceinline__ int wofp(int p) {
    int pp = p & 7;
    return (p >> 3) * 8 + 2 * (pp & 3) + (pp >> 2);
}
__device__ __forceinline__ float ex2(float x) {
    float y;
    asm("ex2.approx.ftz.f32 %0, %1;" : "=f"(y) : "f"(x));
    return y;
}
__device__ __forceinline__ void mma_f16(float* c,
                                        uint32_t a0, uint32_t a1, uint32_t a2, uint32_t a3,
                                        uint32_t b0, uint32_t b1) {
    asm volatile(
        "mma.sync.aligned.m16n8k16.row.col.f32.f16.f16.f32 "
        "{%0,%1,%2,%3},{%4,%5,%6,%7},{%8,%9},{%0,%1,%2,%3};"
        : "+f"(c[0]), "+f"(c[1]), "+f"(c[2]), "+f"(c[3])
        : "r"(a0), "r"(a1), "r"(a2), "r"(a3), "r"(b0), "r"(b1));
}
__device__ __forceinline__ void cp16(void* smem_dst, const void* gsrc) {
    uint32_t s = (uint32_t)__cvta_generic_to_shared(smem_dst);
    asm volatile("cp.async.cg.shared.global [%0], [%1], 16;" :: "r"(s), "l"(gsrc));
}
#define CP_COMMIT() asm volatile("cp.async.commit_group;")
#define CP_WAIT(n)  asm volatile("cp.async.wait_group %0;" :: "n"(n))

// ============================================================================
// Kernel 1: fused prep (unchanged — known good).
// ============================================================================
#define XWROW 72
#define PREP_SMEM (2 * 128 * XWROW * 4)

__global__ void __launch_bounds__(256, 2)
prep_kernel(const float* __restrict__ x,
            const float* __restrict__ Wq, const float* __restrict__ bq,
            const float* __restrict__ Wk, const float* __restrict__ bk) {
    extern __shared__ uint32_t smw[];
    uint32_t* sXw = smw;
    uint32_t* sWw = smw + 128 * XWROW;

    const int tid  = threadIdx.x;
    const int row0 = blockIdx.x * 128;

    for (int i = tid; i < 128 * 32; i += 256) {
        int r = i >> 5, c = i & 31;
        float4 v = *reinterpret_cast<const float4*>(x + (size_t)(row0 + r) * DIN + 4 * c);
        sXw[r * XWROW + wofp(2 * c)]     = packh2(v.x, v.y);
        sXw[r * XWROW + wofp(2 * c + 1)] = packh2(v.z, v.w);
    }
    for (int i = tid; i < 64 * 32; i += 256) {
        int r = i >> 5, c = i & 31;
        float4 vq = *reinterpret_cast<const float4*>(Wq + (size_t)r * DIN + 4 * c);
        float4 vk = *reinterpret_cast<const float4*>(Wk + (size_t)r * DIN + 4 * c);
        sWw[r * XWROW + wofp(2 * c)]            = packh2(vq.x, vq.y);
        sWw[r * XWROW + wofp(2 * c + 1)]        = packh2(vq.z, vq.w);
        sWw[(r + 64) * XWROW + wofp(2 * c)]     = packh2(vk.x, vk.y);
        sWw[(r + 64) * XWROW + wofp(2 * c + 1)] = packh2(vk.z, vk.w);
    }
    __syncthreads();

    const int warp = tid >> 5, lane = tid & 31;
    const int g = lane >> 2, t = lane & 3;
    const int r0 = warp * 16;

    float acc[16][4];
#pragma unroll
    for (int i = 0; i < 16; i++)
#pragma unroll
        for (int j = 0; j < 4; j++) acc[i][j] = 0.f;

#pragma unroll
    for (int kk = 0; kk < 8; kk++) {
        const int wo = kk * 8 + 2 * t;
        uint2 a02 = *reinterpret_cast<const uint2*>(sXw + (r0 + g) * XWROW + wo);
        uint2 a13 = *reinterpret_cast<const uint2*>(sXw + (r0 + g + 8) * XWROW + wo);
#pragma unroll
        for (int nt = 0; nt < 16; nt++) {
            uint2 bv = *reinterpret_cast<const uint2*>(sWw + (nt * 8 + g) * XWROW + wo);
            mma_f16(acc[nt], a02.x, a13.x, a02.y, a13.y, bv.x, bv.y);
        }
    }

    const size_t gr = (size_t)(row0 + r0 + g);
#pragma unroll
    for (int side = 0; side < 2; side++) {
        const float* bias = side ? bk : bq;
        uint32_t* dst = side ? g_KpU : g_QpU;
#pragma unroll
        for (int tq = 0; tq < 8; tq += 2) {
            float* A  = acc[side * 8 + tq];
            float* Bv = acc[side * 8 + tq + 1];
            float b0 = __ldg(bias + tq * 8 + 2 * t);
            float b1 = __ldg(bias + tq * 8 + 2 * t + 1);
            float b2 = __ldg(bias + tq * 8 + 8 + 2 * t);
            float b3 = __ldg(bias + tq * 8 + 8 + 2 * t + 1);
            const int w0 = tq * 4 + 2 * t;
            *reinterpret_cast<uint2*>(dst + gr * 32 + w0) =
                make_uint2(packh2(A[0] + b0, A[1] + b1), packh2(Bv[0] + b2, Bv[1] + b3));
            *reinterpret_cast<uint2*>(dst + (gr + 8) * 32 + w0) =
                make_uint2(packh2(A[2] + b0, A[3] + b1), packh2(Bv[2] + b2, Bv[3] + b3));
        }
    }

    const int b   = row0 >> 11;
    const int mt0 = (row0 & 2047) >> 6;
    for (int j = tid; j < 4096; j += 256) {
        int tile = j >> 11, rem = j & 2047;
        int kkX = rem >> 9, rem2 = rem & 511;
        int p = rem2 >> 3, q = rem2 & 7;
        int pp = (q >> 1) + 4 * (q & 1);
        int mloc = tile * 64 + kkX * 16 + 2 * pp;
        uint32_t u0 = sXw[mloc * XWROW + wofp(p)];
        uint32_t u1 = sXw[(mloc + 1) * XWROW + wofp(p)];
        uint32_t* dst = g_Xh + ((size_t)b * 32 + mt0 + tile) * 4096
                        + kkX * 1024 + (2 * p) * 8 + q;
        dst[0] = prmt(u0, u1, 0x5410);
        dst[8] = prmt(u0, u1, 0x7632);
    }
}

// ============================================================================
// Kernel 2: flash attention, pair-split decomposition.
// Warp (rg = w&3, h = w>>2) owns rows [rg*32, rg*32+32) (two m16 groups).
//  S phase : m-half h   (Q-B bytes halved, B-frags reused across both groups)
//  AV phase: d-half h   (X-B bytes halved, B-frags reused across both groups)
//  P A-frags for the other m-half exchanged with warp w^4 via lane-identical
//  uint4 slots in smem.
// ============================================================================
#define F_THREADS 256
#define KROWW 40
#define W_SQ   5120
#define W_SX   10240
#define W_PX   18432
#define W_NEG  22528
#define W_PART 24576
#define FLASH_SMEM ((W_PART + 256) * 4)

__global__ void __launch_bounds__(F_THREADS, 2)
flash_kernel(const int* __restrict__ mask, float* __restrict__ out) {
    extern __shared__ uint32_t smwf[];
    uint32_t* sK      = smwf;                       // [128][40]
    float*    sNegAll = (float*)(smwf + W_NEG);     // [2048]
    uint4*    sPx     = (uint4*)(smwf + W_PX);      // [8][2][2][32] uint4
    float*    sPart   = (float*)(smwf + W_PART);    // [2][128]

    const int b  = blockIdx.y;
    const int n0 = blockIdx.x * 128;
    const int tid = threadIdx.x;
    const int warp = tid >> 5, lane = tid & 31;
    const int g = lane >> 2, t = lane & 3;
    const int rg = warp & 3, h = warp >> 2;
    const int rA = rg * 32 + g;          // grpA rows: rA, rA+8
    const int rB = rA + 16;              // grpB rows: rB, rB+8

    const uint32_t* Kp = g_KpU + ((size_t)b * N_DIM + n0) * 32;
    const uint32_t* Qb = g_QpU + (size_t)b * N_DIM * 32;
    const uint32_t* Xb = g_Xh + (size_t)b * 32 * 4096;
    const int*      mb = mask + (size_t)b * N_DIM;

    // prologue: G0 = sK + sQ buf0 + sX buf0
    for (int i = tid; i < 128 * 8; i += F_THREADS) {
        int r = i >> 3, c = i & 7;
        cp16(sK + r * KROWW + c * 4, Kp + (size_t)r * 32 + c * 4);
    }
    for (int i = tid; i < 64 * 8; i += F_THREADS) {
        int r = i >> 3, c = i & 7;
        cp16(smwf + W_SQ + r * KROWW + c * 4, Qb + (size_t)r * 32 + c * 4);
    }
    for (int i = tid; i < 1024; i += F_THREADS)
        cp16(smwf + W_SX + i * 4, Xb + (size_t)i * 4);
    CP_COMMIT();

    // preload full neg array
    {
        const int4* m4 = reinterpret_cast<const int4*>(mb);
        for (int i = tid; i < 512; i += F_THREADS) {
            int4 v = __ldg(m4 + i);
            float4 f;
            f.x = (v.x > 0) ? 0.f : MASK_NEG;
            f.y = (v.y > 0) ? 0.f : MASK_NEG;
            f.z = (v.z > 0) ? 0.f : MASK_NEG;
            f.w = (v.w > 0) ? 0.f : MASK_NEG;
            *reinterpret_cast<float4*>(sNegAll + 4 * i) = f;
        }
    }

    float O[2][8][4];       // [grp][d-tile within half][c]
#pragma unroll
    for (int i = 0; i < 2; i++)
#pragma unroll
        for (int j = 0; j < 8; j++)
#pragma unroll
            for (int c = 0; c < 4; c++) O[i][j][c] = 0.f;

    float lrow[4] = {0.f, 0.f, 0.f, 0.f};  // partial sums: grpA g, g+8, grpB g, g+8

    for (int mt = 0; mt < 32; mt++) {
        __syncthreads();   // bufs (mt-1)&1 free; sPx of prev iter fully consumed

        if (mt + 1 < 32) {
            const uint32_t* qn = Qb + (size_t)(mt + 1) * 64 * 32;
            uint32_t* dq = smwf + W_SQ + ((mt + 1) & 1) * 2560;
            for (int i = tid; i < 64 * 8; i += F_THREADS) {
                int r = i >> 3, c = i & 7;
                cp16(dq + r * KROWW + c * 4, qn + (size_t)r * 32 + c * 4);
            }
            const uint32_t* xn = Xb + (size_t)(mt + 1) * 4096;
            uint32_t* dx = smwf + W_SX + ((mt + 1) & 1) * 4096;
            for (int i = tid; i < 1024; i += F_THREADS)
                cp16(dx + i * 4, xn + (size_t)i * 4);
            CP_COMMIT();
            CP_WAIT(1);
        } else {
            CP_WAIT(0);
        }

        const uint32_t* sQ = smwf + W_SQ + (mt & 1) * 2560;
        const uint32_t* sX = smwf + W_SX + (mt & 1) * 4096;

        // ---- S (m-half h) for both row groups; B-frag reused across groups ----
        float S[2][4][4];
#pragma unroll
        for (int i = 0; i < 2; i++)
#pragma unroll
            for (int j = 0; j < 4; j++)
#pragma unroll
                for (int c = 0; c < 4; c++) S[i][j][c] = 0.f;

#pragma unroll
        for (int kk = 0; kk < 4; kk++) {
            const int wo = kk * 8 + 2 * t;
            uint2 aA0 = *reinterpret_cast<const uint2*>(sK + rA * KROWW + wo);
            uint2 aA1 = *reinterpret_cast<const uint2*>(sK + (rA + 8) * KROWW + wo);
            uint2 aB0 = *reinterpret_cast<const uint2*>(sK + rB * KROWW + wo);
            uint2 aB1 = *reinterpret_cast<const uint2*>(sK + (rB + 8) * KROWW + wo);
#pragma unroll
            for (int j = 0; j < 4; j++) {
                uint2 bv = *reinterpret_cast<const uint2*>(
                    sQ + ((h * 4 + j) * 8 + g) * KROWW + wo);
                mma_f16(S[0][j], aA0.x, aA1.x, aA0.y, aA1.y, bv.x, bv.y);
                mma_f16(S[1][j], aB0.x, aB1.x, aB0.y, aB1.y, bv.x, bv.y);
            }
        }

        // ---- softmax (own m-half) + pack own AV A-frags ----
        const float2* ngv = reinterpret_cast<const float2*>(sNegAll + mt * 64);
        uint32_t AF[2][2][4];   // [grp][local kk][word]
#pragma unroll
        for (int gr = 0; gr < 2; gr++) {
            float rs0 = 0.f, rs1 = 0.f;
#pragma unroll
            for (int j = 0; j < 4; j++) {
                float2 ng = ngv[h * 16 + j * 4 + t];
                S[gr][j][0] = ex2(fmaf(S[gr][j][0], SCALE_LOG2E, ng.x));
                S[gr][j][1] = ex2(fmaf(S[gr][j][1], SCALE_LOG2E, ng.y));
                S[gr][j][2] = ex2(fmaf(S[gr][j][2], SCALE_LOG2E, ng.x));
                S[gr][j][3] = ex2(fmaf(S[gr][j][3], SCALE_LOG2E, ng.y));
                rs0 += S[gr][j][0] + S[gr][j][1];
                rs1 += S[gr][j][2] + S[gr][j][3];
            }
#pragma unroll
            for (int kl = 0; kl < 2; kl++) {
                AF[gr][kl][0] = packh2(S[gr][2 * kl][0],     S[gr][2 * kl][1]);
                AF[gr][kl][1] = packh2(S[gr][2 * kl][2],     S[gr][2 * kl][3]);
                AF[gr][kl][2] = packh2(S[gr][2 * kl + 1][0], S[gr][2 * kl + 1][1]);
                AF[gr][kl][3] = packh2(S[gr][2 * kl + 1][2], S[gr][2 * kl + 1][3]);
            }
            rs0 += __shfl_xor_sync(0xffffffffu, rs0, 1);
            rs0 += __shfl_xor_sync(0xffffffffu, rs0, 2);
            rs1 += __shfl_xor_sync(0xffffffffu, rs1, 1);
            rs1 += __shfl_xor_sync(0xffffffffu, rs1, 2);
            lrow[gr * 2]     += rs0;
            lrow[gr * 2 + 1] += rs1;
        }

        // ---- exchange: publish own A-frags for partner (lane-identical) ----
#pragma unroll
        for (int gr = 0; gr < 2; gr++)
#pragma unroll
            for (int kl = 0; kl < 2; kl++)
                sPx[((warp * 2 + gr) * 2 + kl) * 32 + lane] =
                    make_uint4(AF[gr][kl][0], AF[gr][kl][1],
                               AF[gr][kl][2], AF[gr][kl][3]);
        __syncthreads();

        // ---- AV (d-half h) for both row groups; B-frag reused across groups ----
        const int pw = warp ^ 4;
#pragma unroll
        for (int kk = 0; kk < 4; kk++) {
            const int kl = kk & 1;
            uint32_t a[2][4];
            if ((kk >> 1) == h) {
#pragma unroll
                for (int c = 0; c < 4; c++) { a[0][c] = AF[0][kl][c]; a[1][c] = AF[1][kl][c]; }
            } else {
                uint4 v0 = sPx[((pw * 2 + 0) * 2 + kl) * 32 + lane];
                uint4 v1 = sPx[((pw * 2 + 1) * 2 + kl) * 32 + lane];
                a[0][0] = v0.x; a[0][1] = v0.y; a[0][2] = v0.z; a[0][3] = v0.w;
                a[1][0] = v1.x; a[1][1] = v1.y; a[1][2] = v1.z; a[1][3] = v1.w;
            }
            const uint32_t* xk = sX + kk * 1024 + (h * 64) * 8 + 2 * t;
#pragma unroll
            for (int nt = 0; nt < 8; nt++) {
                uint2 bv = *reinterpret_cast<const uint2*>(xk + (nt * 8 + g) * 8);
                mma_f16(O[0][nt], a[0][0], a[0][1], a[0][2], a[0][3], bv.x, bv.y);
                mma_f16(O[1][nt], a[1][0], a[1][1], a[1][2], a[1][3], bv.x, bv.y);
            }
        }
    }

    // ---- epilogue: combine pair row-sums, divide, write out ----
    if (t == 0) {
        sPart[h * 128 + rA]      = lrow[0];
        sPart[h * 128 + rA + 8]  = lrow[1];
        sPart[h * 128 + rB]      = lrow[2];
        sPart[h * 128 + rB + 8]  = lrow[3];
    }
    __syncthreads();
    const float invA0 = 1.f / (sPart[rA]     + sPart[128 + rA]);
    const float invA1 = 1.f / (sPart[rA + 8] + sPart[128 + rA + 8]);
    const float invB0 = 1.f / (sPart[rB]     + sPart[128 + rB]);
    const float invB1 = 1.f / (sPart[rB + 8] + sPart[128 + rB + 8]);

    float* ob = out + ((size_t)b * N_DIM + n0) * DIN + h * 64;
#pragma unroll
    for (int nt = 0; nt < 8; nt++) {
        const int d = nt * 8 + 2 * t;
        *reinterpret_cast<float2*>(ob + (size_t)rA * DIN + d) =
            make_float2(O[0][nt][0] * invA0, O[0][nt][1] * invA0);
        *reinterpret_cast<float2*>(ob + (size_t)(rA + 8) * DIN + d) =
            make_float2(O[0][nt][2] * invA1, O[0][nt][3] * invA1);
        *reinterpret_cast<float2*>(ob + (size_t)rB * DIN + d) =
            make_float2(O[1][nt][0] * invB0, O[1][nt][1] * invB0);
        *reinterpret_cast<float2*>(ob + (size_t)(rB + 8) * DIN + d) =
            make_float2(O[1][nt][2] * invB1, O[1][nt][3] * invB1);
    }
}

// ============================================================================
extern "C" void kernel_launch(void* const* d_in, const int* in_sizes, int n_in,
                              void* d_out, int out_size) {
    const float* x    = (const float*)d_in[0];
    const int*   mask = (const int*)d_in[1];
    const float* Wq   = (const float*)d_in[2];
    const float* bq   = (const float*)d_in[3];
    const float* Wk   = (const float*)d_in[4];
    const float* bk   = (const float*)d_in[5];
    float* out = (float*)d_out;

    cudaFuncSetAttribute(prep_kernel, cudaFuncAttributeMaxDynamicSharedMemorySize, PREP_SMEM);
    cudaFuncSetAttribute(flash_kernel, cudaFuncAttributeMaxDynamicSharedMemorySize, FLASH_SMEM);

    prep_kernel<<<(B_DIM * N_DIM) / 128, 256, PREP_SMEM>>>(x, Wq, bq, Wk, bk);

    dim3 grid(N_DIM / 128, B_DIM);
    flash_kernel<<<grid, 256, FLASH_SMEM>>>(mask, out);
}

// round 14
// speedup vs baseline: 1.0790x; 1.0790x over previous
#include <cuda_runtime.h>
#include <cuda_fp16.h>
#include <cstdint>

#define B_DIM 16
#define N_DIM 2048
#define DIN   128
#define DQv   64

// Qp/Kp: fp16 pair-interleaved words, 32 words per row.
__device__ uint32_t g_QpU[B_DIM * N_DIM * 32];
__device__ uint32_t g_KpU[B_DIM * N_DIM * 32];
// x prepacked: [b][mt(32)][kk(4)][d(136)][q(8)] fp16x2 words (m-pairs).
// d in [0,128): x data; d=128: ones column (row-sum trick); d in (128,136): zeros.
#define XH_MT 4352   // 4 * 136 * 8
__device__ uint32_t g_Xh[B_DIM * 32 * XH_MT];

#define SCALE_LOG2E 0.180336879f
#define MASK_NEG    -30000.0f

__device__ __forceinline__ uint32_t packh2(float lo, float hi) {
    __half2 h = __floats2half2_rn(lo, hi);
    return *reinterpret_cast<uint32_t*>(&h);
}
__device__ __forceinline__ uint32_t prmt(uint32_t a, uint32_t b, uint32_t sel) {
    uint32_t d;
    asm("prmt.b32 %0, %1, %2, %3;" : "=r"(d) : "r"(a), "r"(b), "r"(sel));
    return d;
}
__device__ __forceinline__ int wofp(int p) {
    int pp = p & 7;
    return (p >> 3) * 8 + 2 * (pp & 3) + (pp >> 2);
}
__device__ __forceinline__ uint32_t ex2h2(uint32_t x) {
    uint32_t y;
    asm("ex2.approx.f16x2 %0, %1;" : "=r"(y) : "r"(x));
    return y;
}
__device__ __forceinline__ void mma_f16(float* c,
                                        uint32_t a0, uint32_t a1, uint32_t a2, uint32_t a3,
                                        uint32_t b0, uint32_t b1) {
    asm volatile(
        "mma.sync.aligned.m16n8k16.row.col.f32.f16.f16.f32 "
        "{%0,%1,%2,%3},{%4,%5,%6,%7},{%8,%9},{%0,%1,%2,%3};"
        : "+f"(c[0]), "+f"(c[1]), "+f"(c[2]), "+f"(c[3])
        : "r"(a0), "r"(a1), "r"(a2), "r"(a3), "r"(b0), "r"(b1));
}
__device__ __forceinline__ void cp16(void* smem_dst, const void* gsrc) {
    uint32_t s = (uint32_t)__cvta_generic_to_shared(smem_dst);
    asm volatile("cp.async.cg.shared.global [%0], [%1], 16;" :: "r"(s), "l"(gsrc));
}
#define CP_COMMIT() asm volatile("cp.async.commit_group;")
#define CP_WAIT(n)  asm volatile("cp.async.wait_group %0;" :: "n"(n))

// ============================================================================
// Kernel 1: fused prep (R8/R10 structure + ones-tile emission).
// ============================================================================
#define XWROW 72
#define PREP_SMEM (2 * 128 * XWROW * 4)

__global__ void __launch_bounds__(256, 2)
prep_kernel(const float* __restrict__ x,
            const float* __restrict__ Wq, const float* __restrict__ bq,
            const float* __restrict__ Wk, const float* __restrict__ bk) {
    extern __shared__ uint32_t smw[];
    uint32_t* sXw = smw;
    uint32_t* sWw = smw + 128 * XWROW;

    const int tid  = threadIdx.x;
    const int row0 = blockIdx.x * 128;

    for (int i = tid; i < 128 * 32; i += 256) {
        int r = i >> 5, c = i & 31;
        float4 v = *reinterpret_cast<const float4*>(x + (size_t)(row0 + r) * DIN + 4 * c);
        sXw[r * XWROW + wofp(2 * c)]     = packh2(v.x, v.y);
        sXw[r * XWROW + wofp(2 * c + 1)] = packh2(v.z, v.w);
    }
    for (int i = tid; i < 64 * 32; i += 256) {
        int r = i >> 5, c = i & 31;
        float4 vq = *reinterpret_cast<const float4*>(Wq + (size_t)r * DIN + 4 * c);
        float4 vk = *reinterpret_cast<const float4*>(Wk + (size_t)r * DIN + 4 * c);
        sWw[r * XWROW + wofp(2 * c)]            = packh2(vq.x, vq.y);
        sWw[r * XWROW + wofp(2 * c + 1)]        = packh2(vq.z, vq.w);
        sWw[(r + 64) * XWROW + wofp(2 * c)]     = packh2(vk.x, vk.y);
        sWw[(r + 64) * XWROW + wofp(2 * c + 1)] = packh2(vk.z, vk.w);
    }
    __syncthreads();

    const int warp = tid >> 5, lane = tid & 31;
    const int g = lane >> 2, t = lane & 3;
    const int r0 = warp * 16;

    float acc[16][4];
#pragma unroll
    for (int i = 0; i < 16; i++)
#pragma unroll
        for (int j = 0; j < 4; j++) acc[i][j] = 0.f;

#pragma unroll
    for (int kk = 0; kk < 8; kk++) {
        const int wo = kk * 8 + 2 * t;
        uint2 a02 = *reinterpret_cast<const uint2*>(sXw + (r0 + g) * XWROW + wo);
        uint2 a13 = *reinterpret_cast<const uint2*>(sXw + (r0 + g + 8) * XWROW + wo);
#pragma unroll
        for (int nt = 0; nt < 16; nt++) {
            uint2 bv = *reinterpret_cast<const uint2*>(sWw + (nt * 8 + g) * XWROW + wo);
            mma_f16(acc[nt], a02.x, a13.x, a02.y, a13.y, bv.x, bv.y);
        }
    }

    const size_t gr = (size_t)(row0 + r0 + g);
#pragma unroll
    for (int side = 0; side < 2; side++) {
        const float* bias = side ? bk : bq;
        uint32_t* dst = side ? g_KpU : g_QpU;
#pragma unroll
        for (int tq = 0; tq < 8; tq += 2) {
            float* A  = acc[side * 8 + tq];
            float* Bv = acc[side * 8 + tq + 1];
            float b0 = __ldg(bias + tq * 8 + 2 * t);
            float b1 = __ldg(bias + tq * 8 + 2 * t + 1);
            float b2 = __ldg(bias + tq * 8 + 8 + 2 * t);
            float b3 = __ldg(bias + tq * 8 + 8 + 2 * t + 1);
            const int w0 = tq * 4 + 2 * t;
            *reinterpret_cast<uint2*>(dst + gr * 32 + w0) =
                make_uint2(packh2(A[0] + b0, A[1] + b1), packh2(Bv[0] + b2, Bv[1] + b3));
            *reinterpret_cast<uint2*>(dst + (gr + 8) * 32 + w0) =
                make_uint2(packh2(A[2] + b0, A[3] + b1), packh2(Bv[2] + b2, Bv[3] + b3));
        }
    }

    const int b   = row0 >> 11;
    const int mt0 = (row0 & 2047) >> 6;
    // x data region (d < 128)
    for (int j = tid; j < 4096; j += 256) {
        int tile = j >> 11, rem = j & 2047;
        int kkX = rem >> 9, rem2 = rem & 511;
        int p = rem2 >> 3, q = rem2 & 7;
        int pp = (q >> 1) + 4 * (q & 1);
        int mloc = tile * 64 + kkX * 16 + 2 * pp;
        uint32_t u0 = sXw[mloc * XWROW + wofp(p)];
        uint32_t u1 = sXw[(mloc + 1) * XWROW + wofp(p)];
        uint32_t* dst = g_Xh + ((size_t)b * 32 + mt0 + tile) * XH_MT
                        + kkX * 1088 + (2 * p) * 8 + q;
        dst[0] = prmt(u0, u1, 0x5410);
        dst[8] = prmt(u0, u1, 0x7632);
    }
    // ones/zeros region (d in [128,136)): d==128 -> (1.0h,1.0h), else 0
    for (int j = tid; j < 512; j += 256) {
        int tile = j >> 8, rem = j & 255;
        int kkX = rem >> 6, r = rem & 63;       // r = (d-128)*8 + q
        g_Xh[((size_t)b * 32 + mt0 + tile) * XH_MT + kkX * 1088 + 1024 + r] =
            (r < 8) ? 0x3C003C00u : 0u;
    }
}

// ============================================================================
// Kernel 2: flash attention (R10 structure) + f16x2 ex2 + tensor-core row sums.
// ============================================================================
#define F_THREADS 256
#define KROWW 40
#define W_SQ   5120            // sK: [0, 5120)
#define W_SX   10240           // sQb: [5120,10240), sXb: 2 x 4352 words
#define W_NEG  18944           // sNegAll: 2048 floats
#define FLASH_SMEM ((W_NEG + 2048) * 4)

__global__ void __launch_bounds__(F_THREADS, 2)
flash_kernel(const int* __restrict__ mask, float* __restrict__ out) {
    extern __shared__ uint32_t smwf[];
    uint32_t* sK      = smwf;                     // [128][40]
    float*    sNegAll = (float*)(smwf + W_NEG);   // [2048]

    const int b  = blockIdx.y;
    const int n0 = blockIdx.x * 128;
    const int tid = threadIdx.x;
    const int warp = tid >> 5, lane = tid & 31;
    const int g = lane >> 2, t = lane & 3;
    const int r0 = warp * 16;

    const uint32_t* Kp = g_KpU + ((size_t)b * N_DIM + n0) * 32;
    const uint32_t* Qb = g_QpU + (size_t)b * N_DIM * 32;
    const uint32_t* Xb = g_Xh + (size_t)b * 32 * XH_MT;
    const int*      mb = mask + (size_t)b * N_DIM;

    // prologue: G0 = sK + sQ buf0 + sX buf0
    for (int i = tid; i < 128 * 8; i += F_THREADS) {
        int r = i >> 3, c = i & 7;
        cp16(sK + r * KROWW + c * 4, Kp + (size_t)r * 32 + c * 4);
    }
    for (int i = tid; i < 64 * 8; i += F_THREADS) {
        int r = i >> 3, c = i & 7;
        cp16(smwf + W_SQ + r * KROWW + c * 4, Qb + (size_t)r * 32 + c * 4);
    }
    for (int i = tid; i < 1088; i += F_THREADS)
        cp16(smwf + W_SX + i * 4, Xb + (size_t)i * 4);
    CP_COMMIT();

    // preload full neg array (mask -> 0 / -30000)
    {
        const int4* m4 = reinterpret_cast<const int4*>(mb);
        for (int i = tid; i < 512; i += F_THREADS) {
            int4 v = __ldg(m4 + i);
            float4 f;
            f.x = (v.x > 0) ? 0.f : MASK_NEG;
            f.y = (v.y > 0) ? 0.f : MASK_NEG;
            f.z = (v.z > 0) ? 0.f : MASK_NEG;
            f.w = (v.w > 0) ? 0.f : MASK_NEG;
            *reinterpret_cast<float4*>(sNegAll + 4 * i) = f;
        }
    }

    float O[17][4];                  // tile 16 = ones-column (row sums)
#pragma unroll
    for (int i = 0; i < 17; i++)
#pragma unroll
        for (int j = 0; j < 4; j++) O[i][j] = 0.f;

    for (int mt = 0; mt < 32; mt++) {
        __syncthreads();

        if (mt + 1 < 32) {
            const uint32_t* qn = Qb + (size_t)(mt + 1) * 64 * 32;
            uint32_t* dq = smwf + W_SQ + ((mt + 1) & 1) * 2560;
            for (int i = tid; i < 64 * 8; i += F_THREADS) {
                int r = i >> 3, c = i & 7;
                cp16(dq + r * KROWW + c * 4, qn + (size_t)r * 32 + c * 4);
            }
            const uint32_t* xn = Xb + (size_t)(mt + 1) * XH_MT;
            uint32_t* dx = smwf + W_SX + ((mt + 1) & 1) * XH_MT;
            for (int i = tid; i < 1088; i += F_THREADS)
                cp16(dx + i * 4, xn + (size_t)i * 4);
            CP_COMMIT();
            CP_WAIT(1);
        } else {
            CP_WAIT(0);
        }

        const uint32_t* sQ = smwf + W_SQ + (mt & 1) * 2560;
        const uint32_t* sX = smwf + W_SX + (mt & 1) * XH_MT;

        // ---- S = Kp_tile @ Qp_tile^T ----
        float S[8][4];
#pragma unroll
        for (int i = 0; i < 8; i++)
#pragma unroll
            for (int j = 0; j < 4; j++) S[i][j] = 0.f;

#pragma unroll
        for (int kk = 0; kk < 4; kk++) {
            const int wo = kk * 8 + 2 * t;
            uint2 av0 = *reinterpret_cast<const uint2*>(sK + (r0 + g) * KROWW + wo);
            uint2 av1 = *reinterpret_cast<const uint2*>(sK + (r0 + g + 8) * KROWW + wo);
#pragma unroll
            for (int nt = 0; nt < 8; nt++) {
                uint2 bv = *reinterpret_cast<const uint2*>(sQ + (nt * 8 + g) * KROWW + wo);
                mma_f16(S[nt], av0.x, av1.x, av0.y, av1.y, bv.x, bv.y);
            }
        }

        // ---- P = ex2.f16x2(pack(S*C + neg))  -> fp16 A-frag words directly ----
        const float2* ngv = reinterpret_cast<const float2*>(sNegAll + mt * 64);
        uint32_t E[8][2];
#pragma unroll
        for (int nt = 0; nt < 8; nt++) {
            float2 ng = ngv[nt * 4 + t];
            E[nt][0] = ex2h2(packh2(fmaf(S[nt][0], SCALE_LOG2E, ng.x),
                                    fmaf(S[nt][1], SCALE_LOG2E, ng.y)));
            E[nt][1] = ex2h2(packh2(fmaf(S[nt][2], SCALE_LOG2E, ng.x),
                                    fmaf(S[nt][3], SCALE_LOG2E, ng.y)));
        }

        // ---- O += P @ X  (17th tile accumulates row sums via ones column) ----
#pragma unroll
        for (int kk = 0; kk < 4; kk++) {
            uint32_t a0 = E[2 * kk][0];
            uint32_t a1 = E[2 * kk][1];
            uint32_t a2 = E[2 * kk + 1][0];
            uint32_t a3 = E[2 * kk + 1][1];
            const uint32_t* xk = sX + kk * 1088 + 2 * t;
#pragma unroll
            for (int nt = 0; nt < 17; nt++) {
                uint2 bv = *reinterpret_cast<const uint2*>(xk + (nt * 8 + g) * 8);
                mma_f16(O[nt], a0, a1, a2, a3, bv.x, bv.y);
            }
        }
    }

    // ---- epilogue: row sums live in O[16] col d=128 (threads with t==0) ----
    const int qlead = lane & 28;   // lane of t=0 in this quad
    const float sum0 = __shfl_sync(0xffffffffu, O[16][0], qlead);
    const float sum1 = __shfl_sync(0xffffffffu, O[16][2], qlead);
    const float inv0 = 1.f / sum0;
    const float inv1 = 1.f / sum1;

    float* ob = out + ((size_t)b * N_DIM + n0 + r0) * DIN;
#pragma unroll
    for (int nt = 0; nt < 16; nt++) {
        const int d = nt * 8 + 2 * t;
        *reinterpret_cast<float2*>(ob + (size_t)g * DIN + d) =
            make_float2(O[nt][0] * inv0, O[nt][1] * inv0);
        *reinterpret_cast<float2*>(ob + (size_t)(g + 8) * DIN + d) =
            make_float2(O[nt][2] * inv1, O[nt][3] * inv1);
    }
}

// ============================================================================
extern "C" void kernel_launch(void* const* d_in, const int* in_sizes, int n_in,
                              void* d_out, int out_size) {
    const float* x    = (const float*)d_in[0];
    const int*   mask = (const int*)d_in[1];
    const float* Wq   = (const float*)d_in[2];
    const float* bq   = (const float*)d_in[3];
    const float* Wk   = (const float*)d_in[4];
    const float* bk   = (const float*)d_in[5];
    float* out = (float*)d_out;

    cudaFuncSetAttribute(prep_kernel, cudaFuncAttributeMaxDynamicSharedMemorySize, PREP_SMEM);
    cudaFuncSetAttribute(flash_kernel, cudaFuncAttributeMaxDynamicSharedMemorySize, FLASH_SMEM);

    prep_kernel<<<(B_DIM * N_DIM) / 128, 256, PREP_SMEM>>>(x, Wq, bq, Wk, bk);

    dim3 grid(N_DIM / 128, B_DIM);
    flash_kernel<<<grid, 256, FLASH_SMEM>>>(mask, out);
}

// round 17
// speedup vs baseline: 1.1173x; 1.0355x over previous
#include <cuda_runtime.h>
#include <cuda_fp16.h>
#include <cstdint>

#define B_DIM 16
#define N_DIM 2048
#define DIN   128
#define DQv   64

// Qp/Kp: fp16 pair-interleaved words, 32 words per row.
__device__ uint32_t g_QpU[B_DIM * N_DIM * 32];
__device__ uint32_t g_KpU[B_DIM * N_DIM * 32];
// x prepacked: [b][mt(32)][kk(4)][d(136)][q(8)] fp16x2 words (m-pairs).
// d in [0,128): x data; d=128: ones column (row-sum trick); d in (128,136): zeros.
#define XH_MT 4352   // 4 * 136 * 8
__device__ uint32_t g_Xh[B_DIM * 32 * XH_MT];

#define SCALE_LOG2E 0.180336879f
#define MASK_NEG    -30000.0f

__device__ __forceinline__ uint32_t packh2(float lo, float hi) {
    __half2 h = __floats2half2_rn(lo, hi);
    return *reinterpret_cast<uint32_t*>(&h);
}
__device__ __forceinline__ uint32_t prmt(uint32_t a, uint32_t b, uint32_t sel) {
    uint32_t d;
    asm("prmt.b32 %0, %1, %2, %3;" : "=r"(d) : "r"(a), "r"(b), "r"(sel));
    return d;
}
__device__ __forceinline__ int wofp(int p) {
    int pp = p & 7;
    return (p >> 3) * 8 + 2 * (pp & 3) + (pp >> 2);
}
__device__ __forceinline__ uint32_t ex2h2(uint32_t x) {
    uint32_t y;
    asm("ex2.approx.f16x2 %0, %1;" : "=r"(y) : "r"(x));
    return y;
}
__device__ __forceinline__ void mma_f16(float* c,
                                        uint32_t a0, uint32_t a1, uint32_t a2, uint32_t a3,
                                        uint32_t b0, uint32_t b1) {
    asm volatile(
        "mma.sync.aligned.m16n8k16.row.col.f32.f16.f16.f32 "
        "{%0,%1,%2,%3},{%4,%5,%6,%7},{%8,%9},{%0,%1,%2,%3};"
        : "+f"(c[0]), "+f"(c[1]), "+f"(c[2]), "+f"(c[3])
        : "r"(a0), "r"(a1), "r"(a2), "r"(a3), "r"(b0), "r"(b1));
}
__device__ __forceinline__ void cp16(void* smem_dst, const void* gsrc) {
    uint32_t s = (uint32_t)__cvta_generic_to_shared(smem_dst);
    asm volatile("cp.async.cg.shared.global [%0], [%1], 16;" :: "r"(s), "l"(gsrc));
}
__device__ __forceinline__ void mbar_init(uint32_t mbar, uint32_t cnt) {
    asm volatile("mbarrier.init.shared.b64 [%0], %1;" :: "r"(mbar), "r"(cnt) : "memory");
}
__device__ __forceinline__ void mbar_arrive(uint32_t mbar) {
    asm volatile("mbarrier.arrive.shared.b64 _, [%0];" :: "r"(mbar) : "memory");
}
__device__ __forceinline__ void mbar_cp_arrive(uint32_t mbar) {
    asm volatile("cp.async.mbarrier.arrive.shared::cta.b64 [%0];" :: "r"(mbar) : "memory");
}
__device__ __forceinline__ void mbar_wait(uint32_t mbar, uint32_t parity) {
    asm volatile(
        "{\n\t.reg .pred P1;\n"
        "W%=:\n\t"
        "mbarrier.try_wait.parity.acquire.cta.shared::cta.b64 P1, [%0], %1, 0x989680;\n\t"
        "@P1 bra D%=;\n\t"
        "bra.uni W%=;\n"
        "D%=:\n\t}"
        :: "r"(mbar), "r"(parity) : "memory");
}

// ============================================================================
// Kernel 1: fused prep (unchanged — known good).
// ============================================================================
#define XWROW 72
#define PREP_SMEM (2 * 128 * XWROW * 4)

__global__ void __launch_bounds__(256, 2)
prep_kernel(const float* __restrict__ x,
            const float* __restrict__ Wq, const float* __restrict__ bq,
            const float* __restrict__ Wk, const float* __restrict__ bk) {
    extern __shared__ uint32_t smw[];
    uint32_t* sXw = smw;
    uint32_t* sWw = smw + 128 * XWROW;

    const int tid  = threadIdx.x;
    const int row0 = blockIdx.x * 128;

    for (int i = tid; i < 128 * 32; i += 256) {
        int r = i >> 5, c = i & 31;
        float4 v = *reinterpret_cast<const float4*>(x + (size_t)(row0 + r) * DIN + 4 * c);
        sXw[r * XWROW + wofp(2 * c)]     = packh2(v.x, v.y);
        sXw[r * XWROW + wofp(2 * c + 1)] = packh2(v.z, v.w);
    }
    for (int i = tid; i < 64 * 32; i += 256) {
        int r = i >> 5, c = i & 31;
        float4 vq = *reinterpret_cast<const float4*>(Wq + (size_t)r * DIN + 4 * c);
        float4 vk = *reinterpret_cast<const float4*>(Wk + (size_t)r * DIN + 4 * c);
        sWw[r * XWROW + wofp(2 * c)]            = packh2(vq.x, vq.y);
        sWw[r * XWROW + wofp(2 * c + 1)]        = packh2(vq.z, vq.w);
        sWw[(r + 64) * XWROW + wofp(2 * c)]     = packh2(vk.x, vk.y);
        sWw[(r + 64) * XWROW + wofp(2 * c + 1)] = packh2(vk.z, vk.w);
    }
    __syncthreads();

    const int warp = tid >> 5, lane = tid & 31;
    const int g = lane >> 2, t = lane & 3;
    const int r0 = warp * 16;

    float acc[16][4];
#pragma unroll
    for (int i = 0; i < 16; i++)
#pragma unroll
        for (int j = 0; j < 4; j++) acc[i][j] = 0.f;

#pragma unroll
    for (int kk = 0; kk < 8; kk++) {
        const int wo = kk * 8 + 2 * t;
        uint2 a02 = *reinterpret_cast<const uint2*>(sXw + (r0 + g) * XWROW + wo);
        uint2 a13 = *reinterpret_cast<const uint2*>(sXw + (r0 + g + 8) * XWROW + wo);
#pragma unroll
        for (int nt = 0; nt < 16; nt++) {
            uint2 bv = *reinterpret_cast<const uint2*>(sWw + (nt * 8 + g) * XWROW + wo);
            mma_f16(acc[nt], a02.x, a13.x, a02.y, a13.y, bv.x, bv.y);
        }
    }

    const size_t gr = (size_t)(row0 + r0 + g);
#pragma unroll
    for (int side = 0; side < 2; side++) {
        const float* bias = side ? bk : bq;
        uint32_t* dst = side ? g_KpU : g_QpU;
#pragma unroll
        for (int tq = 0; tq < 8; tq += 2) {
            float* A  = acc[side * 8 + tq];
            float* Bv = acc[side * 8 + tq + 1];
            float b0 = __ldg(bias + tq * 8 + 2 * t);
            float b1 = __ldg(bias + tq * 8 + 2 * t + 1);
            float b2 = __ldg(bias + tq * 8 + 8 + 2 * t);
            float b3 = __ldg(bias + tq * 8 + 8 + 2 * t + 1);
            const int w0 = tq * 4 + 2 * t;
            *reinterpret_cast<uint2*>(dst + gr * 32 + w0) =
                make_uint2(packh2(A[0] + b0, A[1] + b1), packh2(Bv[0] + b2, Bv[1] + b3));
            *reinterpret_cast<uint2*>(dst + (gr + 8) * 32 + w0) =
                make_uint2(packh2(A[2] + b0, A[3] + b1), packh2(Bv[2] + b2, Bv[3] + b3));
        }
    }

    const int b   = row0 >> 11;
    const int mt0 = (row0 & 2047) >> 6;
    for (int j = tid; j < 4096; j += 256) {
        int tile = j >> 11, rem = j & 2047;
        int kkX = rem >> 9, rem2 = rem & 511;
        int p = rem2 >> 3, q = rem2 & 7;
        int pp = (q >> 1) + 4 * (q & 1);
        int mloc = tile * 64 + kkX * 16 + 2 * pp;
        uint32_t u0 = sXw[mloc * XWROW + wofp(p)];
        uint32_t u1 = sXw[(mloc + 1) * XWROW + wofp(p)];
        uint32_t* dst = g_Xh + ((size_t)b * 32 + mt0 + tile) * XH_MT
                        + kkX * 1088 + (2 * p) * 8 + q;
        dst[0] = prmt(u0, u1, 0x5410);
        dst[8] = prmt(u0, u1, 0x7632);
    }
    for (int j = tid; j < 512; j += 256) {
        int tile = j >> 8, rem = j & 255;
        int kkX = rem >> 6, r = rem & 63;
        g_Xh[((size_t)b * 32 + mt0 + tile) * XH_MT + kkX * 1088 + 1024 + r] =
            (r < 8) ? 0x3C003C00u : 0u;
    }
}

// ============================================================================
// Kernel 2: flash attention, mbarrier 3-stage pipeline, no mainloop barrier.
// full[] init = 256 (regular arrivals only); cp.async.mbarrier.arrive
// self-cancels (inc at issue, arrive on completion) and is NOT counted.
// ============================================================================
#define F_THREADS 256
#define KROWW 40
#define STG_W  6912                       // per stage: sQ 2560 + sX 4352
#define W_STG  5120                       // sK: [0, 5120)
#define W_NEG  (W_STG + 3 * STG_W)        // 25856: sNegAll 2048 floats
#define W_MBAR (W_NEG + 2048)             // 27904: full[3], empty[3] (2w each)
#define FLASH_SMEM ((W_MBAR + 16) * 4)

__global__ void __launch_bounds__(F_THREADS, 2)
flash_kernel(const int* __restrict__ mask, float* __restrict__ out) {
    extern __shared__ uint32_t smwf[];
    uint32_t* sK      = smwf;                     // [128][40]
    float*    sNegAll = (float*)(smwf + W_NEG);   // [2048]

    const int b  = blockIdx.y;
    const int n0 = blockIdx.x * 128;
    const int tid = threadIdx.x;
    const int warp = tid >> 5, lane = tid & 31;
    const int g = lane >> 2, t = lane & 3;
    const int r0 = warp * 16;

    const uint32_t mbarBase = (uint32_t)__cvta_generic_to_shared(smwf + W_MBAR);
    // full[s] = mbarBase + s*8 ; empty[s] = mbarBase + 24 + s*8
    if (tid == 0) {
#pragma unroll
        for (int s = 0; s < 3; s++) {
            mbar_init(mbarBase + s * 8, 256);        // regular arrivals only
            mbar_init(mbarBase + 24 + s * 8, 256);   // all threads arrive
        }
    }
    __syncthreads();   // mbarrier init visible; only barrier in the kernel

    const uint32_t* Kp = g_KpU + ((size_t)b * N_DIM + n0) * 32;
    const uint32_t* Qb = g_QpU + (size_t)b * N_DIM * 32;
    const uint32_t* Xb = g_Xh + (size_t)b * 32 * XH_MT;
    const int*      mb = mask + (size_t)b * N_DIM;

    // ---- fill stage f into buffer f%3, then arrive on full[f%3] ----
    auto stage_fill = [&](int f) {
        uint32_t* dq = smwf + W_STG + (f % 3) * STG_W;
        uint32_t* dx = dq + 2560;
        const uint32_t* qn = Qb + (size_t)f * 64 * 32;
        const uint32_t* xn = Xb + (size_t)f * XH_MT;
        for (int i = tid; i < 512; i += F_THREADS) {
            int r = i >> 3, c = i & 7;
            cp16(dq + r * KROWW + c * 4, qn + (size_t)r * 32 + c * 4);
        }
        for (int i = tid; i < 1088; i += F_THREADS)
            cp16(dx + i * 4, xn + (size_t)i * 4);
        mbar_cp_arrive(mbarBase + (f % 3) * 8);   // holds phase until copies land
        mbar_arrive(mbarBase + (f % 3) * 8);      // counted arrival (release)
    };

    // prologue: sK + neg + stages 0,1
    for (int i = tid; i < 128 * 8; i += F_THREADS) {
        int r = i >> 3, c = i & 7;
        cp16(sK + r * KROWW + c * 4, Kp + (size_t)r * 32 + c * 4);
    }
    {
        const int4* m4 = reinterpret_cast<const int4*>(mb);
        for (int i = tid; i < 512; i += F_THREADS) {
            int4 v = __ldg(m4 + i);
            float4 f;
            f.x = (v.x > 0) ? 0.f : MASK_NEG;
            f.y = (v.y > 0) ? 0.f : MASK_NEG;
            f.z = (v.z > 0) ? 0.f : MASK_NEG;
            f.w = (v.w > 0) ? 0.f : MASK_NEG;
            *reinterpret_cast<float4*>(sNegAll + 4 * i) = f;
        }
    }
    stage_fill(0);   // cp-arrive on full[0] also covers sK copies; regular
                     // arrive (release) publishes the neg STS
    stage_fill(1);

    float O[17][4];                  // tile 16 = ones-column (row sums)
#pragma unroll
    for (int i = 0; i < 17; i++)
#pragma unroll
        for (int j = 0; j < 4; j++) O[i][j] = 0.f;

    for (int mt = 0; mt < 32; mt++) {
        const int buf = mt % 3;
        mbar_wait(mbarBase + buf * 8, (mt / 3) & 1);   // fill #mt/3 complete

        const uint32_t* sQ = smwf + W_STG + buf * STG_W;
        const uint32_t* sX = sQ + 2560;

        // ---- S = Kp_tile @ Qp_tile^T ----
        float S[8][4];
#pragma unroll
        for (int i = 0; i < 8; i++)
#pragma unroll
            for (int j = 0; j < 4; j++) S[i][j] = 0.f;

#pragma unroll
        for (int kk = 0; kk < 4; kk++) {
            const int wo = kk * 8 + 2 * t;
            uint2 av0 = *reinterpret_cast<const uint2*>(sK + (r0 + g) * KROWW + wo);
            uint2 av1 = *reinterpret_cast<const uint2*>(sK + (r0 + g + 8) * KROWW + wo);
#pragma unroll
            for (int nt = 0; nt < 8; nt++) {
                uint2 bv = *reinterpret_cast<const uint2*>(sQ + (nt * 8 + g) * KROWW + wo);
                mma_f16(S[nt], av0.x, av1.x, av0.y, av1.y, bv.x, bv.y);
            }
        }

        // ---- P = ex2.f16x2(pack(S*C + neg)) -> fp16 A-frag words ----
        const float2* ngv = reinterpret_cast<const float2*>(sNegAll + mt * 64);
        uint32_t E[8][2];
#pragma unroll
        for (int nt = 0; nt < 8; nt++) {
            float2 ng = ngv[nt * 4 + t];
            E[nt][0] = ex2h2(packh2(fmaf(S[nt][0], SCALE_LOG2E, ng.x),
                                    fmaf(S[nt][1], SCALE_LOG2E, ng.y)));
            E[nt][1] = ex2h2(packh2(fmaf(S[nt][2], SCALE_LOG2E, ng.x),
                                    fmaf(S[nt][3], SCALE_LOG2E, ng.y)));
        }

        // ---- O += P @ X  (17th tile = row sums via ones column) ----
#pragma unroll
        for (int kk = 0; kk < 4; kk++) {
            uint32_t a0 = E[2 * kk][0];
            uint32_t a1 = E[2 * kk][1];
            uint32_t a2 = E[2 * kk + 1][0];
            uint32_t a3 = E[2 * kk + 1][1];
            const uint32_t* xk = sX + kk * 1088 + 2 * t;
#pragma unroll
            for (int nt = 0; nt < 17; nt++) {
                uint2 bv = *reinterpret_cast<const uint2*>(xk + (nt * 8 + g) * 8);
                mma_f16(O[nt], a0, a1, a2, a3, bv.x, bv.y);
            }
        }

        mbar_arrive(mbarBase + 24 + buf * 8);          // emptied buffer buf

        // ---- stage fill f = mt+2 (after own compute -> max overlap) ----
        const int f = mt + 2;
        if (f < 32) {
            if (f >= 3)
                mbar_wait(mbarBase + 24 + (f % 3) * 8, ((f / 3) - 1) & 1);
            stage_fill(f);
        }
    }

    // ---- epilogue: row sums in O[16] cols (t==0 threads) ----
    const int qlead = lane & 28;
    const float sum0 = __shfl_sync(0xffffffffu, O[16][0], qlead);
    const float sum1 = __shfl_sync(0xffffffffu, O[16][2], qlead);
    const float inv0 = 1.f / sum0;
    const float inv1 = 1.f / sum1;

    float* ob = out + ((size_t)b * N_DIM + n0 + r0) * DIN;
#pragma unroll
    for (int nt = 0; nt < 16; nt++) {
        const int d = nt * 8 + 2 * t;
        *reinterpret_cast<float2*>(ob + (size_t)g * DIN + d) =
            make_float2(O[nt][0] * inv0, O[nt][1] * inv0);
        *reinterpret_cast<float2*>(ob + (size_t)(g + 8) * DIN + d) =
            make_float2(O[nt][2] * inv1, O[nt][3] * inv1);
    }
}

// ============================================================================
extern "C" void kernel_launch(void* const* d_in, const int* in_sizes, int n_in,
                              void* d_out, int out_size) {
    const float* x    = (const float*)d_in[0];
    const int*   mask = (const int*)d_in[1];
    const float* Wq   = (const float*)d_in[2];
    const float* bq   = (const float*)d_in[3];
    const float* Wk   = (const float*)d_in[4];
    const float* bk   = (const float*)d_in[5];
    float* out = (float*)d_out;

    cudaFuncSetAttribute(prep_kernel, cudaFuncAttributeMaxDynamicSharedMemorySize, PREP_SMEM);
    cudaFuncSetAttribute(flash_kernel, cudaFuncAttributeMaxDynamicSharedMemorySize, FLASH_SMEM);

    prep_kernel<<<(B_DIM * N_DIM) / 128, 256, PREP_SMEM>>>(x, Wq, bq, Wk, bk);

    dim3 grid(N_DIM / 128, B_DIM);
    flash_kernel<<<grid, 256, FLASH_SMEM>>>(mask, out);
}